// round 13
// baseline (speedup 1.0000x reference)
#include <cuda_runtime.h>
#include <cuda_fp16.h>
#include <cstdint>

#define NN   100000
#define EE   1600000
#define F_IN 128
#define HID  64
#define OUTD 40

// Scratch (device globals — allocation is forbidden)
__device__ __half g_uA[NN * HID];
__device__ __half g_uB[NN * HID];
__device__ int    g_deg[NN];
__device__ float  g_dis[NN];
__device__ __half g_dish[NN];
__device__ int    g_rowptr[NN];
__device__ int    g_cursor[NN];
__device__ int    g_colidx[EE];
__device__ int    g_bsum[128];

#define XSTR 132           // 128 rows + 4 pad (16B-aligned k-rows)
#define WS_FLOATS (64 * 64)
#define XS_FLOATS (64 * XSTR)
#define SMEM_BYTES ((WS_FLOATS + XS_FLOATS) * 4)   // 50176

__device__ __forceinline__ unsigned long long pack2(float x) {
    unsigned long long r;
    asm("mov.b64 %0, {%1, %2};" : "=l"(r) : "f"(x), "f"(x));
    return r;
}

// 4x8 inner product over one K=64 chunk. Rows tiy*4..+3 (of 128), cols tix*8..+7.
__device__ __forceinline__ void gemm_4x8_chunk(const float* Ws, const float* Xs,
                                               int tix, int tiy,
                                               unsigned long long acc[4][4]) {
    #pragma unroll
    for (int k = 0; k < 64; k++) {
        ulonglong2 wA = *reinterpret_cast<const ulonglong2*>(&Ws[k * 64 + tix * 8]);
        ulonglong2 wB = *reinterpret_cast<const ulonglong2*>(&Ws[k * 64 + tix * 8 + 4]);
        float4 xr = *reinterpret_cast<const float4*>(&Xs[k * XSTR + tiy * 4]);
        unsigned long long xp;
        xp = pack2(xr.x);
        asm("fma.rn.f32x2 %0, %1, %2, %0;" : "+l"(acc[0][0]) : "l"(xp), "l"(wA.x));
        asm("fma.rn.f32x2 %0, %1, %2, %0;" : "+l"(acc[0][1]) : "l"(xp), "l"(wA.y));
        asm("fma.rn.f32x2 %0, %1, %2, %0;" : "+l"(acc[0][2]) : "l"(xp), "l"(wB.x));
        asm("fma.rn.f32x2 %0, %1, %2, %0;" : "+l"(acc[0][3]) : "l"(xp), "l"(wB.y));
        xp = pack2(xr.y);
        asm("fma.rn.f32x2 %0, %1, %2, %0;" : "+l"(acc[1][0]) : "l"(xp), "l"(wA.x));
        asm("fma.rn.f32x2 %0, %1, %2, %0;" : "+l"(acc[1][1]) : "l"(xp), "l"(wA.y));
        asm("fma.rn.f32x2 %0, %1, %2, %0;" : "+l"(acc[1][2]) : "l"(xp), "l"(wB.x));
        asm("fma.rn.f32x2 %0, %1, %2, %0;" : "+l"(acc[1][3]) : "l"(xp), "l"(wB.y));
        xp = pack2(xr.z);
        asm("fma.rn.f32x2 %0, %1, %2, %0;" : "+l"(acc[2][0]) : "l"(xp), "l"(wA.x));
        asm("fma.rn.f32x2 %0, %1, %2, %0;" : "+l"(acc[2][1]) : "l"(xp), "l"(wA.y));
        asm("fma.rn.f32x2 %0, %1, %2, %0;" : "+l"(acc[2][2]) : "l"(xp), "l"(wB.x));
        asm("fma.rn.f32x2 %0, %1, %2, %0;" : "+l"(acc[2][3]) : "l"(xp), "l"(wB.y));
        xp = pack2(xr.w);
        asm("fma.rn.f32x2 %0, %1, %2, %0;" : "+l"(acc[3][0]) : "l"(xp), "l"(wA.x));
        asm("fma.rn.f32x2 %0, %1, %2, %0;" : "+l"(acc[3][1]) : "l"(xp), "l"(wA.y));
        asm("fma.rn.f32x2 %0, %1, %2, %0;" : "+l"(acc[3][2]) : "l"(xp), "l"(wB.x));
        asm("fma.rn.f32x2 %0, %1, %2, %0;" : "+l"(acc[3][3]) : "l"(xp), "l"(wB.y));
    }
}

__device__ __forceinline__ uint4 finish_row_half(const unsigned long long a[4],
                                                 const float4& bA, const float4& bB,
                                                 float s) {
    float o[8];
    o[0] = (__uint_as_float((unsigned)(a[0] & 0xffffffffu)) + bA.x) * s;
    o[1] = (__uint_as_float((unsigned)(a[0] >> 32))         + bA.y) * s;
    o[2] = (__uint_as_float((unsigned)(a[1] & 0xffffffffu)) + bA.z) * s;
    o[3] = (__uint_as_float((unsigned)(a[1] >> 32))         + bA.w) * s;
    o[4] = (__uint_as_float((unsigned)(a[2] & 0xffffffffu)) + bB.x) * s;
    o[5] = (__uint_as_float((unsigned)(a[2] >> 32))         + bB.y) * s;
    o[6] = (__uint_as_float((unsigned)(a[3] & 0xffffffffu)) + bB.z) * s;
    o[7] = (__uint_as_float((unsigned)(a[3] >> 32))         + bB.w) * s;
    __half2 h0 = __floats2half2_rn(o[0], o[1]);
    __half2 h1 = __floats2half2_rn(o[2], o[3]);
    __half2 h2 = __floats2half2_rn(o[4], o[5]);
    __half2 h3 = __floats2half2_rn(o[6], o[7]);
    return make_uint4(*(unsigned*)&h0, *(unsigned*)&h1, *(unsigned*)&h2, *(unsigned*)&h3);
}

// ---------------------------------------------------------------------------
// Prep chain
// ---------------------------------------------------------------------------
__global__ void count_deg_kernel(const int* __restrict__ dst, int E, int* __restrict__ deg) {
    int e = blockIdx.x * blockDim.x + threadIdx.x;
    if (e < E) atomicAdd(&deg[dst[e]], 1);
}

__global__ void scan1_kernel(const int* __restrict__ deg, int* __restrict__ rowptr,
                             float* __restrict__ dis, __half* __restrict__ dish,
                             int* __restrict__ bsum, int n) {
    __shared__ int sh[256];
    int t = threadIdx.x;
    int base = blockIdx.x * 1024 + t * 4;
    int v[4]; int s = 0;
    #pragma unroll
    for (int j = 0; j < 4; j++) {
        v[j] = (base + j < n) ? deg[base + j] : 0;
        if (base + j < n) {
            float r = rsqrtf((float)(v[j] + 1));
            dis[base + j] = r;
            dish[base + j] = __float2half_rn(r);
        }
        s += v[j];
    }
    sh[t] = s;
    for (int off = 1; off < 256; off <<= 1) {
        __syncthreads();
        int x = (t >= off) ? sh[t - off] : 0;
        __syncthreads();
        sh[t] += x;
    }
    __syncthreads();
    int excl = sh[t] - s;
    int run = 0;
    #pragma unroll
    for (int j = 0; j < 4; j++) {
        if (base + j < n) rowptr[base + j] = excl + run;
        run += v[j];
    }
    if (t == 255) bsum[blockIdx.x] = sh[255];
}

__global__ void scan3_kernel(const int* __restrict__ bsum, int* __restrict__ rowptr,
                             int* __restrict__ cursor, int n, int nb) {
    __shared__ int sh[128];
    int t = threadIdx.x;
    if (t < 128) sh[t] = (t < nb) ? bsum[t] : 0;
    __syncthreads();
    for (int off = 1; off < 128; off <<= 1) {
        int x = (t < 128 && t >= off) ? sh[t - off] : 0;
        __syncthreads();
        if (t < 128) sh[t] += x;
        __syncthreads();
    }
    int i = blockIdx.x * blockDim.x + t;
    if (i < n) {
        int c = i >> 10;
        int excl = (c == 0) ? 0 : sh[c - 1];
        int r = rowptr[i] + excl;
        rowptr[i] = r;
        cursor[i] = r;
    }
}

// ---------------------------------------------------------------------------
// Layer-0 GEMM (128x64 tile, 256 thr at 4x8) + fused edge scatter.
// ---------------------------------------------------------------------------
__global__ void gemm0_scatter_kernel(const float* __restrict__ X,
                                     const float* __restrict__ W,
                                     const float* __restrict__ B,
                                     __half* __restrict__ u, int n,
                                     const int* __restrict__ src,
                                     const int* __restrict__ dst,
                                     int* __restrict__ cursor,
                                     int* __restrict__ colidx, int E,
                                     int gemmBlocks) {
    extern __shared__ float smem[];
    float* Ws = smem;
    float* Xs = smem + WS_FLOATS;

    int t = threadIdx.x;

    if ((int)blockIdx.x >= gemmBlocks) {
        int e = (blockIdx.x - gemmBlocks) * 256 + t;
        if (e < E) {
            int p = atomicAdd(&cursor[dst[e]], 1);
            colidx[p] = src[e];
        }
        return;
    }

    int row0 = blockIdx.x * 128;
    int tix = t & 7;
    int tiy = t >> 3;

    unsigned long long acc[4][4];
    #pragma unroll
    for (int r = 0; r < 4; r++)
        #pragma unroll
        for (int c = 0; c < 4; c++) acc[r][c] = 0ull;

    for (int k0 = 0; k0 < F_IN; k0 += 64) {
        // W chunk [64 k][64 cols]
        #pragma unroll
        for (int i = t; i < WS_FLOATS / 4; i += 256)
            ((float4*)Ws)[i] = ((const float4*)(W + k0 * 64))[i];
        // X chunk transposed to Xs[k][row], 128 rows
        #pragma unroll
        for (int i = t; i < 128 * 16; i += 256) {
            int r = i >> 4;
            int c4 = (i & 15) * 4;
            int gr = row0 + r;
            float4 x = {0.f, 0.f, 0.f, 0.f};
            if (gr < n) x = *(const float4*)(X + (size_t)gr * F_IN + k0 + c4);
            Xs[(c4 + 0) * XSTR + r] = x.x;
            Xs[(c4 + 1) * XSTR + r] = x.y;
            Xs[(c4 + 2) * XSTR + r] = x.z;
            Xs[(c4 + 3) * XSTR + r] = x.w;
        }
        __syncthreads();

        gemm_4x8_chunk(Ws, Xs, tix, tiy, acc);
        __syncthreads();
    }

    float4 bA = *(const float4*)(B + tix * 8);
    float4 bB = *(const float4*)(B + tix * 8 + 4);
    #pragma unroll
    for (int r = 0; r < 4; r++) {
        int gr = row0 + tiy * 4 + r;
        if (gr >= n) continue;
        uint4 pk = finish_row_half(acc[r], bA, bB, 1.f);
        *(uint4*)(u + (size_t)gr * 64 + tix * 8) = pk;
    }
}

// ---------------------------------------------------------------------------
// Aggregate node v with 4 lanes (lane h covers halfs [h*16, h*16+16)).
// Proven R11 form: unroll 2, two fp16 accumulator sets; fp32 combine.
// ---------------------------------------------------------------------------
template<bool WEIGHTED>
__device__ __forceinline__ void aggregate_node4(
    int v, int h,
    const int* __restrict__ rowptr, const int* __restrict__ deg,
    const int* __restrict__ colidx, const float* __restrict__ dis,
    const __half* __restrict__ dish, const __half* __restrict__ u,
    float out[16])
{
    const uint4* uv = (const uint4*)u;   // row stride = 8 uint4; lane h uses slots h*2, h*2+1
    const __half2 z = __float2half2_rn(0.f);
    __half2 s0[8], s1[8];
    #pragma unroll
    for (int k = 0; k < 8; k++) { s0[k] = z; s1[k] = z; }

    int p0 = __ldg(rowptr + v);
    int d  = __ldg(deg + v);
    int base = h * 2;

    int j = 0;
    for (; j + 2 <= d; j += 2) {
        int c0 = __ldg(colidx + p0 + j);
        int c1 = __ldg(colidx + p0 + j + 1);
        uint4 a0 = __ldg(uv + (size_t)c0 * 8 + base);
        uint4 a1 = __ldg(uv + (size_t)c0 * 8 + base + 1);
        uint4 b0 = __ldg(uv + (size_t)c1 * 8 + base);
        uint4 b1 = __ldg(uv + (size_t)c1 * 8 + base + 1);
        if (WEIGHTED) {
            __half2 w0 = __half2half2(__ldg(dish + c0));
            __half2 w1 = __half2half2(__ldg(dish + c1));
            #pragma unroll
            for (int k = 0; k < 4; k++) {
                s0[k]     = __hfma2(w0, ((__half2*)&a0)[k], s0[k]);
                s0[k + 4] = __hfma2(w0, ((__half2*)&a1)[k], s0[k + 4]);
                s1[k]     = __hfma2(w1, ((__half2*)&b0)[k], s1[k]);
                s1[k + 4] = __hfma2(w1, ((__half2*)&b1)[k], s1[k + 4]);
            }
        } else {
            #pragma unroll
            for (int k = 0; k < 4; k++) {
                s0[k]     = __hadd2(s0[k],     ((__half2*)&a0)[k]);
                s0[k + 4] = __hadd2(s0[k + 4], ((__half2*)&a1)[k]);
                s1[k]     = __hadd2(s1[k],     ((__half2*)&b0)[k]);
                s1[k + 4] = __hadd2(s1[k + 4], ((__half2*)&b1)[k]);
            }
        }
    }
    if (j < d) {
        int c0 = __ldg(colidx + p0 + j);
        uint4 a0 = __ldg(uv + (size_t)c0 * 8 + base);
        uint4 a1 = __ldg(uv + (size_t)c0 * 8 + base + 1);
        if (WEIGHTED) {
            __half2 w0 = __half2half2(__ldg(dish + c0));
            #pragma unroll
            for (int k = 0; k < 4; k++) {
                s0[k]     = __hfma2(w0, ((__half2*)&a0)[k], s0[k]);
                s0[k + 4] = __hfma2(w0, ((__half2*)&a1)[k], s0[k + 4]);
            }
        } else {
            #pragma unroll
            for (int k = 0; k < 4; k++) {
                s0[k]     = __hadd2(s0[k],     ((__half2*)&a0)[k]);
                s0[k + 4] = __hadd2(s0[k + 4], ((__half2*)&a1)[k]);
            }
        }
    }

    uint4 p0v = __ldg(uv + (size_t)v * 8 + base);
    uint4 p1v = __ldg(uv + (size_t)v * 8 + base + 1);
    float dv = __ldg(dis + v);
    float sv = WEIGHTED ? dv : 1.f;

    #pragma unroll
    for (int k = 0; k < 8; k++) {
        float2 f0 = __half22float2(s0[k]);
        float2 f1 = __half22float2(s1[k]);
        __half2 psk = (k < 4) ? ((__half2*)&p0v)[k] : ((__half2*)&p1v)[k - 4];
        float2 fs = __half22float2(psk);
        float a0 = f0.x + f1.x + fs.x * sv;
        float a1 = f0.y + f1.y + fs.y * sv;
        out[k * 2 + 0] = fmaxf(a0, 0.f) * dv;
        out[k * 2 + 1] = fmaxf(a1, 0.f) * dv;
    }
}

// ---------------------------------------------------------------------------
// Fused pull + GEMM64: 128-node tile. Phase 1 = two 64-node halves with the
// proven 4-lane aggregation; phase 2 = 128x64 GEMM, all 256 threads at 4x8.
// ---------------------------------------------------------------------------
template<bool WEIGHTED>
__global__ void fused64_kernel(const int* __restrict__ rowptr,
                               const int* __restrict__ deg,
                               const int* __restrict__ colidx,
                               const float* __restrict__ dis,
                               const __half* __restrict__ dish,
                               const __half* __restrict__ u_in,
                               const float* __restrict__ W,
                               const float* __restrict__ B,
                               __half* __restrict__ u_out, int n) {
    extern __shared__ float smem[];
    float* Ws = smem;
    float* Xs = smem + WS_FLOATS;

    int t = threadIdx.x;
    int row0 = blockIdx.x * 128;

    #pragma unroll
    for (int i = t; i < WS_FLOATS / 4; i += 256)
        ((float4*)Ws)[i] = ((const float4*)W)[i];

    // Phase 1: aggregate 128 nodes in two halves of 64 (4 lanes per node)
    #pragma unroll
    for (int half = 0; half < 2; half++) {
        int r = half * 64 + (t >> 2);
        int h = t & 3;
        int v = row0 + r;
        float xv[16];
        #pragma unroll
        for (int k = 0; k < 16; k++) xv[k] = 0.f;
        if (v < n)
            aggregate_node4<WEIGHTED>(v, h, rowptr, deg, colidx, dis, dish, u_in, xv);
        #pragma unroll
        for (int k = 0; k < 16; k++)
            Xs[(h * 16 + k) * XSTR + r] = xv[k];
    }
    __syncthreads();

    // Phase 2: 128x64 GEMM
    int tix = t & 7;
    int tiy = t >> 3;
    unsigned long long acc[4][4];
    #pragma unroll
    for (int r = 0; r < 4; r++)
        #pragma unroll
        for (int c = 0; c < 4; c++) acc[r][c] = 0ull;

    gemm_4x8_chunk(Ws, Xs, tix, tiy, acc);

    float4 bA = *(const float4*)(B + tix * 8);
    float4 bB = *(const float4*)(B + tix * 8 + 4);
    #pragma unroll
    for (int r = 0; r < 4; r++) {
        int gr = row0 + tiy * 4 + r;
        if (gr >= n) continue;
        float s = __ldg(dis + gr);
        uint4 pk = finish_row_half(acc[r], bA, bB, s);
        *(uint4*)(u_out + (size_t)gr * 64 + tix * 8) = pk;
    }
}

// ---------------------------------------------------------------------------
// Aggregate node v with 8 lanes (head kernel, unchanged).
// ---------------------------------------------------------------------------
__device__ __forceinline__ void aggregate_node8(
    int v, int h,
    const int* __restrict__ rowptr, const int* __restrict__ deg,
    const int* __restrict__ colidx, const float* __restrict__ dis,
    const __half* __restrict__ u,
    float out[8])
{
    const uint4* uv = (const uint4*)u;
    const __half2 z = __float2half2_rn(0.f);
    __half2 s0[4] = {z, z, z, z};
    __half2 s1[4] = {z, z, z, z};

    int p0 = __ldg(rowptr + v);
    int d  = __ldg(deg + v);

    int j = 0;
    for (; j + 2 <= d; j += 2) {
        int c0 = __ldg(colidx + p0 + j);
        int c1 = __ldg(colidx + p0 + j + 1);
        uint4 x0 = __ldg(uv + (size_t)c0 * 8 + h);
        uint4 x1 = __ldg(uv + (size_t)c1 * 8 + h);
        #pragma unroll
        for (int k = 0; k < 4; k++) {
            s0[k] = __hadd2(s0[k], ((__half2*)&x0)[k]);
            s1[k] = __hadd2(s1[k], ((__half2*)&x1)[k]);
        }
    }
    if (j < d) {
        int c0 = __ldg(colidx + p0 + j);
        uint4 x0 = __ldg(uv + (size_t)c0 * 8 + h);
        #pragma unroll
        for (int k = 0; k < 4; k++)
            s0[k] = __hadd2(s0[k], ((__half2*)&x0)[k]);
    }

    uint4 ps = __ldg(uv + (size_t)v * 8 + h);
    float dv = __ldg(dis + v);

    #pragma unroll
    for (int k = 0; k < 4; k++) {
        float2 f0 = __half22float2(s0[k]);
        float2 f1 = __half22float2(s1[k]);
        float2 fs = __half22float2(((__half2*)&ps)[k]);
        out[k * 2 + 0] = fmaxf(f0.x + f1.x + fs.x, 0.f) * dv;
        out[k * 2 + 1] = fmaxf(f0.y + f1.y + fs.y, 0.f) * dv;
    }
}

// ---------------------------------------------------------------------------
// Fused pull + head GEMM (K=64, NOUT=40), fp32 output. 32-row tile.
// ---------------------------------------------------------------------------
__global__ void fused_head_kernel(const int* __restrict__ rowptr,
                                  const int* __restrict__ deg,
                                  const int* __restrict__ colidx,
                                  const float* __restrict__ dis,
                                  const __half* __restrict__ u_in,
                                  const float* __restrict__ W,
                                  const float* __restrict__ B,
                                  float* __restrict__ out, int n) {
    constexpr int K = HID, NOUT = OUTD;
    __shared__ float Ws2[K * NOUT];
    __shared__ float Xs2[32 * K];

    int t = threadIdx.x;
    int row0 = blockIdx.x * 32;

    #pragma unroll 4
    for (int i = t; i < K * NOUT; i += 256) Ws2[i] = W[i];

    {
        int r = t >> 3;
        int h = t & 7;
        int v = row0 + r;
        float xv[8] = {0,0,0,0,0,0,0,0};
        if (v < n)
            aggregate_node8(v, h, rowptr, deg, colidx, dis, u_in, xv);
        float* p = &Xs2[r * K + h * 8];
        #pragma unroll
        for (int k = 0; k < 8; k++) p[k] = xv[k];
    }
    __syncthreads();

    int warp = t >> 5, lane = t & 31;
    int r0 = warp * 4;
    float acc0[4] = {0.f, 0.f, 0.f, 0.f};
    float acc1[4] = {0.f, 0.f, 0.f, 0.f};

    #pragma unroll
    for (int k = 0; k < K; k++) {
        float w0 = Ws2[k * NOUT + lane];
        float w1 = (lane + 32 < NOUT) ? Ws2[k * NOUT + lane + 32] : 0.f;
        #pragma unroll
        for (int r = 0; r < 4; r++) {
            float xv = Xs2[(r0 + r) * K + k];
            acc0[r] = fmaf(xv, w0, acc0[r]);
            acc1[r] = fmaf(xv, w1, acc1[r]);
        }
    }

    float b0 = B[lane];
    float b1 = (lane + 32 < NOUT) ? B[lane + 32] : 0.f;
    #pragma unroll
    for (int r = 0; r < 4; r++) {
        int gr = row0 + r0 + r;
        if (gr >= n) continue;
        out[(size_t)gr * NOUT + lane] = acc0[r] + b0;
        if (lane + 32 < NOUT) out[(size_t)gr * NOUT + lane + 32] = acc1[r] + b1;
    }
}

// ---------------------------------------------------------------------------
extern "C" void kernel_launch(void* const* d_in, const int* in_sizes, int n_in,
                              void* d_out, int out_size) {
    const float* x    = (const float*)d_in[0];
    const int*   ei   = (const int*)d_in[1];
    const float* W0   = (const float*)d_in[2];
    const float* b0   = (const float*)d_in[3];
    const float* W1   = (const float*)d_in[4];
    const float* b1   = (const float*)d_in[5];
    const float* W2   = (const float*)d_in[6];
    const float* b2   = (const float*)d_in[7];
    const float* Wout = (const float*)d_in[8];
    const float* bout = (const float*)d_in[9];
    float* out = (float*)d_out;

    const int N = in_sizes[0] / F_IN;
    const int E = in_sizes[1] / 2;
    const int* src = ei;
    const int* dst = ei + E;

    __half *uA, *uB, *dish;
    float *dis;
    int *deg, *rowptr, *cursor, *colidx, *bsum;
    cudaGetSymbolAddress((void**)&uA,     g_uA);
    cudaGetSymbolAddress((void**)&uB,     g_uB);
    cudaGetSymbolAddress((void**)&deg,    g_deg);
    cudaGetSymbolAddress((void**)&dis,    g_dis);
    cudaGetSymbolAddress((void**)&dish,   g_dish);
    cudaGetSymbolAddress((void**)&rowptr, g_rowptr);
    cudaGetSymbolAddress((void**)&cursor, g_cursor);
    cudaGetSymbolAddress((void**)&colidx, g_colidx);
    cudaGetSymbolAddress((void**)&bsum,   g_bsum);

    // Raise dynamic smem limits (runs at capture time; not part of the graph)
    static bool attr_set = false;
    if (!attr_set) {
        cudaFuncSetAttribute(gemm0_scatter_kernel,
                             cudaFuncAttributeMaxDynamicSharedMemorySize, SMEM_BYTES);
        cudaFuncSetAttribute(fused64_kernel<true>,
                             cudaFuncAttributeMaxDynamicSharedMemorySize, SMEM_BYTES);
        cudaFuncSetAttribute(fused64_kernel<false>,
                             cudaFuncAttributeMaxDynamicSharedMemorySize, SMEM_BYTES);
        attr_set = true;
    }

    const int TPB = 256;
    int gemmBlocks128 = (N + 127) / 128;            // 782
    int scatB = (E + TPB - 1) / TPB;                // 6250
    dim3 mega_grid(gemmBlocks128 + scatB);
    dim3 layer_grid(gemmBlocks128);
    dim3 head_grid((N + 31) / 32);
    int nscan = (N + 1023) / 1024;

    // CSR prerequisite chain
    cudaMemsetAsync(deg, 0, N * sizeof(int), 0);
    count_deg_kernel<<<(E + TPB - 1) / TPB, TPB>>>(dst, E, deg);
    scan1_kernel<<<nscan, 256>>>(deg, rowptr, dis, dish, bsum, N);
    scan3_kernel<<<(N + TPB - 1) / TPB, TPB>>>(bsum, rowptr, cursor, N, nscan);

    // Layer-0 GEMM overlapped with CSR edge scatter
    gemm0_scatter_kernel<<<mega_grid, TPB, SMEM_BYTES>>>(
        x, W0, b0, uA, N, src, dst, cursor, colidx, E, gemmBlocks128);

    // Fused layers
    fused64_kernel<true><<<layer_grid, TPB, SMEM_BYTES>>>(rowptr, deg, colidx, dis, dish, uA, W1, b1, uB, N);
    fused64_kernel<false><<<layer_grid, TPB, SMEM_BYTES>>>(rowptr, deg, colidx, dis, dish, uB, W2, b2, uA, N);
    fused_head_kernel<<<head_grid, TPB>>>(rowptr, deg, colidx, dis, uA, Wout, bout, out, N);
}

// round 14
// speedup vs baseline: 1.4907x; 1.4907x over previous
#include <cuda_runtime.h>
#include <cuda_fp16.h>
#include <mma.h>
#include <cstdint>

using namespace nvcuda;

#define NN   100000
#define EE   1600000
#define F_IN 128
#define HID  64
#define OUTD 40

// Scratch (device globals — allocation is forbidden)
__device__ __half g_uA[NN * HID];
__device__ __half g_uB[NN * HID];
__device__ int    g_deg[NN];
__device__ float  g_dis[NN];
__device__ __half g_dish[NN];
__device__ int    g_rowptr[NN];
__device__ int    g_cursor[NN];
__device__ int    g_colidx[EE];
__device__ int    g_bsum[128];

#define XH_STR 72     // halfs per row (64 + 8 pad); 144B row stride, 16B-aligned
#define X0_STR 136    // gemm0 X row stride in halfs (128 + 8 pad); 272B
#define CS_STR 68     // floats per row (64 + 4 pad); 272B

// ---------------------------------------------------------------------------
// Prep chain
// ---------------------------------------------------------------------------
__global__ void count_deg_kernel(const int* __restrict__ dst, int E, int* __restrict__ deg) {
    int e = blockIdx.x * blockDim.x + threadIdx.x;
    if (e < E) atomicAdd(&deg[dst[e]], 1);
}

__global__ void scan1_kernel(const int* __restrict__ deg, int* __restrict__ rowptr,
                             float* __restrict__ dis, __half* __restrict__ dish,
                             int* __restrict__ bsum, int n) {
    __shared__ int sh[256];
    int t = threadIdx.x;
    int base = blockIdx.x * 1024 + t * 4;
    int v[4]; int s = 0;
    #pragma unroll
    for (int j = 0; j < 4; j++) {
        v[j] = (base + j < n) ? deg[base + j] : 0;
        if (base + j < n) {
            float r = rsqrtf((float)(v[j] + 1));
            dis[base + j] = r;
            dish[base + j] = __float2half_rn(r);
        }
        s += v[j];
    }
    sh[t] = s;
    for (int off = 1; off < 256; off <<= 1) {
        __syncthreads();
        int x = (t >= off) ? sh[t - off] : 0;
        __syncthreads();
        sh[t] += x;
    }
    __syncthreads();
    int excl = sh[t] - s;
    int run = 0;
    #pragma unroll
    for (int j = 0; j < 4; j++) {
        if (base + j < n) rowptr[base + j] = excl + run;
        run += v[j];
    }
    if (t == 255) bsum[blockIdx.x] = sh[255];
}

__global__ void scan3_kernel(const int* __restrict__ bsum, int* __restrict__ rowptr,
                             int* __restrict__ cursor, int n, int nb) {
    __shared__ int sh[128];
    int t = threadIdx.x;
    if (t < 128) sh[t] = (t < nb) ? bsum[t] : 0;
    __syncthreads();
    for (int off = 1; off < 128; off <<= 1) {
        int x = (t < 128 && t >= off) ? sh[t - off] : 0;
        __syncthreads();
        if (t < 128) sh[t] += x;
        __syncthreads();
    }
    int i = blockIdx.x * blockDim.x + t;
    if (i < n) {
        int c = i >> 10;
        int excl = (c == 0) ? 0 : sh[c - 1];
        int r = rowptr[i] + excl;
        rowptr[i] = r;
        cursor[i] = r;
    }
}

// ---------------------------------------------------------------------------
// Shared WMMA helpers
// ---------------------------------------------------------------------------
// Convert a [64 k][64 n] fp32 weight block to fp16 smem tile (stride XH_STR).
__device__ __forceinline__ void load_weights_h(const float* __restrict__ W,
                                               __half* Wh, int t) {
    #pragma unroll
    for (int i = t; i < 64 * 64 / 4; i += 256) {
        float4 w = ((const float4*)W)[i];
        int r = (i * 4) >> 6;
        int c = (i * 4) & 63;
        __half2 h0 = __floats2half2_rn(w.x, w.y);
        __half2 h1 = __floats2half2_rn(w.z, w.w);
        *(uint2*)&Wh[r * XH_STR + c] = make_uint2(*(unsigned*)&h0, *(unsigned*)&h1);
    }
}

// ---------------------------------------------------------------------------
// Layer-0 GEMM via WMMA (64-row tile, K=128 in two chunks) + fused scatter.
// ---------------------------------------------------------------------------
__global__ void gemm0_scatter_kernel(const float* __restrict__ X,
                                     const float* __restrict__ W,
                                     const float* __restrict__ B,
                                     __half* __restrict__ u, int n,
                                     const int* __restrict__ src,
                                     const int* __restrict__ dst,
                                     int* __restrict__ cursor,
                                     int* __restrict__ colidx, int E,
                                     int gemmBlocks) {
    __shared__ __half Xh[64 * X0_STR];   // 17408 B
    __shared__ __half Wh[64 * XH_STR];   //  9216 B
    __shared__ float  Cs[64 * CS_STR];   // 17408 B

    int t = threadIdx.x;

    if ((int)blockIdx.x >= gemmBlocks) {
        int e = (blockIdx.x - gemmBlocks) * 256 + t;
        if (e < E) {
            int p = atomicAdd(&cursor[dst[e]], 1);
            colidx[p] = src[e];
        }
        return;
    }

    int row0 = blockIdx.x * 64;

    // Load X [64][128] fp32 -> fp16 Xh
    #pragma unroll
    for (int i = t; i < 64 * F_IN / 4; i += 256) {
        int r = (i * 4) >> 7;          // /128
        int c = (i * 4) & 127;
        int gr = row0 + r;
        float4 x = {0.f, 0.f, 0.f, 0.f};
        if (gr < n) x = *(const float4*)(X + (size_t)gr * F_IN + c);
        __half2 h0 = __floats2half2_rn(x.x, x.y);
        __half2 h1 = __floats2half2_rn(x.z, x.w);
        *(uint2*)&Xh[r * X0_STR + c] = make_uint2(*(unsigned*)&h0, *(unsigned*)&h1);
    }

    int wp = t >> 5;
    int rt = wp >> 1;            // row tile 0..3
    int ct0 = (wp & 1) * 2;      // col tiles ct0, ct0+1

    wmma::fragment<wmma::accumulator, 16, 16, 16, float> c0, c1;
    wmma::fill_fragment(c0, 0.f);
    wmma::fill_fragment(c1, 0.f);

    for (int chunk = 0; chunk < 2; chunk++) {
        load_weights_h(W + chunk * 64 * 64, Wh, t);
        __syncthreads();
        #pragma unroll
        for (int kk = 0; kk < 4; kk++) {
            wmma::fragment<wmma::matrix_a, 16, 16, 16, __half, wmma::row_major> a;
            wmma::load_matrix_sync(a, &Xh[rt * 16 * X0_STR + chunk * 64 + kk * 16], X0_STR);
            wmma::fragment<wmma::matrix_b, 16, 16, 16, __half, wmma::row_major> b;
            wmma::load_matrix_sync(b, &Wh[kk * 16 * XH_STR + ct0 * 16], XH_STR);
            wmma::mma_sync(c0, a, b, c0);
            wmma::load_matrix_sync(b, &Wh[kk * 16 * XH_STR + (ct0 + 1) * 16], XH_STR);
            wmma::mma_sync(c1, a, b, c1);
        }
        __syncthreads();
    }

    wmma::store_matrix_sync(&Cs[rt * 16 * CS_STR + ct0 * 16], c0, CS_STR, wmma::mem_row_major);
    wmma::store_matrix_sync(&Cs[rt * 16 * CS_STR + (ct0 + 1) * 16], c1, CS_STR, wmma::mem_row_major);
    __syncthreads();

    // Epilogue: + bias, fp16 out (unscaled)
    {
        int r = t >> 2;
        int c = (t & 3) * 16;
        int gr = row0 + r;
        if (gr < n) {
            __half2 hh[8];
            #pragma unroll
            for (int k = 0; k < 8; k++) {
                float v0 = Cs[r * CS_STR + c + k * 2]     + B[c + k * 2];
                float v1 = Cs[r * CS_STR + c + k * 2 + 1] + B[c + k * 2 + 1];
                hh[k] = __floats2half2_rn(v0, v1);
            }
            uint4* dst4 = (uint4*)(u + (size_t)gr * 64 + c);
            dst4[0] = make_uint4(*(unsigned*)&hh[0], *(unsigned*)&hh[1],
                                 *(unsigned*)&hh[2], *(unsigned*)&hh[3]);
            dst4[1] = make_uint4(*(unsigned*)&hh[4], *(unsigned*)&hh[5],
                                 *(unsigned*)&hh[6], *(unsigned*)&hh[7]);
        }
    }
}

// ---------------------------------------------------------------------------
// Aggregate node v with 4 lanes (proven R11 form).
// ---------------------------------------------------------------------------
template<bool WEIGHTED>
__device__ __forceinline__ void aggregate_node4(
    int v, int h,
    const int* __restrict__ rowptr, const int* __restrict__ deg,
    const int* __restrict__ colidx, const float* __restrict__ dis,
    const __half* __restrict__ dish, const __half* __restrict__ u,
    float out[16])
{
    const uint4* uv = (const uint4*)u;
    const __half2 z = __float2half2_rn(0.f);
    __half2 s0[8], s1[8];
    #pragma unroll
    for (int k = 0; k < 8; k++) { s0[k] = z; s1[k] = z; }

    int p0 = __ldg(rowptr + v);
    int d  = __ldg(deg + v);
    int base = h * 2;

    int j = 0;
    for (; j + 2 <= d; j += 2) {
        int c0 = __ldg(colidx + p0 + j);
        int c1 = __ldg(colidx + p0 + j + 1);
        uint4 a0 = __ldg(uv + (size_t)c0 * 8 + base);
        uint4 a1 = __ldg(uv + (size_t)c0 * 8 + base + 1);
        uint4 b0 = __ldg(uv + (size_t)c1 * 8 + base);
        uint4 b1 = __ldg(uv + (size_t)c1 * 8 + base + 1);
        if (WEIGHTED) {
            __half2 w0 = __half2half2(__ldg(dish + c0));
            __half2 w1 = __half2half2(__ldg(dish + c1));
            #pragma unroll
            for (int k = 0; k < 4; k++) {
                s0[k]     = __hfma2(w0, ((__half2*)&a0)[k], s0[k]);
                s0[k + 4] = __hfma2(w0, ((__half2*)&a1)[k], s0[k + 4]);
                s1[k]     = __hfma2(w1, ((__half2*)&b0)[k], s1[k]);
                s1[k + 4] = __hfma2(w1, ((__half2*)&b1)[k], s1[k + 4]);
            }
        } else {
            #pragma unroll
            for (int k = 0; k < 4; k++) {
                s0[k]     = __hadd2(s0[k],     ((__half2*)&a0)[k]);
                s0[k + 4] = __hadd2(s0[k + 4], ((__half2*)&a1)[k]);
                s1[k]     = __hadd2(s1[k],     ((__half2*)&b0)[k]);
                s1[k + 4] = __hadd2(s1[k + 4], ((__half2*)&b1)[k]);
            }
        }
    }
    if (j < d) {
        int c0 = __ldg(colidx + p0 + j);
        uint4 a0 = __ldg(uv + (size_t)c0 * 8 + base);
        uint4 a1 = __ldg(uv + (size_t)c0 * 8 + base + 1);
        if (WEIGHTED) {
            __half2 w0 = __half2half2(__ldg(dish + c0));
            #pragma unroll
            for (int k = 0; k < 4; k++) {
                s0[k]     = __hfma2(w0, ((__half2*)&a0)[k], s0[k]);
                s0[k + 4] = __hfma2(w0, ((__half2*)&a1)[k], s0[k + 4]);
            }
        } else {
            #pragma unroll
            for (int k = 0; k < 4; k++) {
                s0[k]     = __hadd2(s0[k],     ((__half2*)&a0)[k]);
                s0[k + 4] = __hadd2(s0[k + 4], ((__half2*)&a1)[k]);
            }
        }
    }

    uint4 p0v = __ldg(uv + (size_t)v * 8 + base);
    uint4 p1v = __ldg(uv + (size_t)v * 8 + base + 1);
    float dv = __ldg(dis + v);
    float sv = WEIGHTED ? dv : 1.f;

    #pragma unroll
    for (int k = 0; k < 8; k++) {
        float2 f0 = __half22float2(s0[k]);
        float2 f1 = __half22float2(s1[k]);
        __half2 psk = (k < 4) ? ((__half2*)&p0v)[k] : ((__half2*)&p1v)[k - 4];
        float2 fs = __half22float2(psk);
        float a0 = f0.x + f1.x + fs.x * sv;
        float a1 = f0.y + f1.y + fs.y * sv;
        out[k * 2 + 0] = fmaxf(a0, 0.f) * dv;
        out[k * 2 + 1] = fmaxf(a1, 0.f) * dv;
    }
}

// ---------------------------------------------------------------------------
// Fused pull + WMMA GEMM64. 64-node tile; phase 1 writes fp16 rows into Xh.
// ---------------------------------------------------------------------------
template<bool WEIGHTED>
__global__ void fused64_kernel(const int* __restrict__ rowptr,
                               const int* __restrict__ deg,
                               const int* __restrict__ colidx,
                               const float* __restrict__ dis,
                               const __half* __restrict__ dish,
                               const __half* __restrict__ u_in,
                               const float* __restrict__ W,
                               const float* __restrict__ B,
                               __half* __restrict__ u_out, int n) {
    __shared__ __half Xh[64 * XH_STR];   // 9216 B
    __shared__ __half Wh[64 * XH_STR];   // 9216 B
    __shared__ float  Cs[64 * CS_STR];   // 17408 B

    int t = threadIdx.x;
    int row0 = blockIdx.x * 64;

    load_weights_h(W, Wh, t);

    // Phase 1: aggregate 64 nodes (4 lanes each) -> Xh row-major fp16
    {
        int r = t >> 2;
        int h = t & 3;
        int v = row0 + r;
        float xv[16];
        #pragma unroll
        for (int k = 0; k < 16; k++) xv[k] = 0.f;
        if (v < n)
            aggregate_node4<WEIGHTED>(v, h, rowptr, deg, colidx, dis, dish, u_in, xv);
        __half2 hh[8];
        #pragma unroll
        for (int k = 0; k < 8; k++)
            hh[k] = __floats2half2_rn(xv[k * 2], xv[k * 2 + 1]);
        uint4* p = (uint4*)&Xh[r * XH_STR + h * 16];
        p[0] = make_uint4(*(unsigned*)&hh[0], *(unsigned*)&hh[1],
                          *(unsigned*)&hh[2], *(unsigned*)&hh[3]);
        p[1] = make_uint4(*(unsigned*)&hh[4], *(unsigned*)&hh[5],
                          *(unsigned*)&hh[6], *(unsigned*)&hh[7]);
    }
    __syncthreads();

    // Phase 2: WMMA 64x64 = Xh @ Wh (fp32 accumulate)
    int wp = t >> 5;
    int rt = wp >> 1;
    int ct0 = (wp & 1) * 2;

    wmma::fragment<wmma::accumulator, 16, 16, 16, float> c0, c1;
    wmma::fill_fragment(c0, 0.f);
    wmma::fill_fragment(c1, 0.f);

    #pragma unroll
    for (int kk = 0; kk < 4; kk++) {
        wmma::fragment<wmma::matrix_a, 16, 16, 16, __half, wmma::row_major> a;
        wmma::load_matrix_sync(a, &Xh[rt * 16 * XH_STR + kk * 16], XH_STR);
        wmma::fragment<wmma::matrix_b, 16, 16, 16, __half, wmma::row_major> b;
        wmma::load_matrix_sync(b, &Wh[kk * 16 * XH_STR + ct0 * 16], XH_STR);
        wmma::mma_sync(c0, a, b, c0);
        wmma::load_matrix_sync(b, &Wh[kk * 16 * XH_STR + (ct0 + 1) * 16], XH_STR);
        wmma::mma_sync(c1, a, b, c1);
    }
    wmma::store_matrix_sync(&Cs[rt * 16 * CS_STR + ct0 * 16], c0, CS_STR, wmma::mem_row_major);
    wmma::store_matrix_sync(&Cs[rt * 16 * CS_STR + (ct0 + 1) * 16], c1, CS_STR, wmma::mem_row_major);
    __syncthreads();

    // Epilogue: + bias, * dis[row], fp16 out
    {
        int r = t >> 2;
        int c = (t & 3) * 16;
        int gr = row0 + r;
        if (gr < n) {
            float s = __ldg(dis + gr);
            __half2 hh[8];
            #pragma unroll
            for (int k = 0; k < 8; k++) {
                float v0 = (Cs[r * CS_STR + c + k * 2]     + B[c + k * 2])     * s;
                float v1 = (Cs[r * CS_STR + c + k * 2 + 1] + B[c + k * 2 + 1]) * s;
                hh[k] = __floats2half2_rn(v0, v1);
            }
            uint4* dst4 = (uint4*)(u_out + (size_t)gr * 64 + c);
            dst4[0] = make_uint4(*(unsigned*)&hh[0], *(unsigned*)&hh[1],
                                 *(unsigned*)&hh[2], *(unsigned*)&hh[3]);
            dst4[1] = make_uint4(*(unsigned*)&hh[4], *(unsigned*)&hh[5],
                                 *(unsigned*)&hh[6], *(unsigned*)&hh[7]);
        }
    }
}

// ---------------------------------------------------------------------------
// Aggregate node v with 8 lanes (head kernel, unchanged).
// ---------------------------------------------------------------------------
__device__ __forceinline__ void aggregate_node8(
    int v, int h,
    const int* __restrict__ rowptr, const int* __restrict__ deg,
    const int* __restrict__ colidx, const float* __restrict__ dis,
    const __half* __restrict__ u,
    float out[8])
{
    const uint4* uv = (const uint4*)u;
    const __half2 z = __float2half2_rn(0.f);
    __half2 s0[4] = {z, z, z, z};
    __half2 s1[4] = {z, z, z, z};

    int p0 = __ldg(rowptr + v);
    int d  = __ldg(deg + v);

    int j = 0;
    for (; j + 2 <= d; j += 2) {
        int c0 = __ldg(colidx + p0 + j);
        int c1 = __ldg(colidx + p0 + j + 1);
        uint4 x0 = __ldg(uv + (size_t)c0 * 8 + h);
        uint4 x1 = __ldg(uv + (size_t)c1 * 8 + h);
        #pragma unroll
        for (int k = 0; k < 4; k++) {
            s0[k] = __hadd2(s0[k], ((__half2*)&x0)[k]);
            s1[k] = __hadd2(s1[k], ((__half2*)&x1)[k]);
        }
    }
    if (j < d) {
        int c0 = __ldg(colidx + p0 + j);
        uint4 x0 = __ldg(uv + (size_t)c0 * 8 + h);
        #pragma unroll
        for (int k = 0; k < 4; k++)
            s0[k] = __hadd2(s0[k], ((__half2*)&x0)[k]);
    }

    uint4 ps = __ldg(uv + (size_t)v * 8 + h);
    float dv = __ldg(dis + v);

    #pragma unroll
    for (int k = 0; k < 4; k++) {
        float2 f0 = __half22float2(s0[k]);
        float2 f1 = __half22float2(s1[k]);
        float2 fs = __half22float2(((__half2*)&ps)[k]);
        out[k * 2 + 0] = fmaxf(f0.x + f1.x + fs.x, 0.f) * dv;
        out[k * 2 + 1] = fmaxf(f0.y + f1.y + fs.y, 0.f) * dv;
    }
}

// ---------------------------------------------------------------------------
// Fused pull + head GEMM (K=64, NOUT=40), fp32 output. 32-row tile.
// ---------------------------------------------------------------------------
__global__ void fused_head_kernel(const int* __restrict__ rowptr,
                                  const int* __restrict__ deg,
                                  const int* __restrict__ colidx,
                                  const float* __restrict__ dis,
                                  const __half* __restrict__ u_in,
                                  const float* __restrict__ W,
                                  const float* __restrict__ B,
                                  float* __restrict__ out, int n) {
    constexpr int K = HID, NOUT = OUTD;
    __shared__ float Ws2[K * NOUT];
    __shared__ float Xs2[32 * K];

    int t = threadIdx.x;
    int row0 = blockIdx.x * 32;

    #pragma unroll 4
    for (int i = t; i < K * NOUT; i += 256) Ws2[i] = W[i];

    {
        int r = t >> 3;
        int h = t & 7;
        int v = row0 + r;
        float xv[8] = {0,0,0,0,0,0,0,0};
        if (v < n)
            aggregate_node8(v, h, rowptr, deg, colidx, dis, u_in, xv);
        float* p = &Xs2[r * K + h * 8];
        #pragma unroll
        for (int k = 0; k < 8; k++) p[k] = xv[k];
    }
    __syncthreads();

    int warp = t >> 5, lane = t & 31;
    int r0 = warp * 4;
    float acc0[4] = {0.f, 0.f, 0.f, 0.f};
    float acc1[4] = {0.f, 0.f, 0.f, 0.f};

    #pragma unroll
    for (int k = 0; k < K; k++) {
        float w0 = Ws2[k * NOUT + lane];
        float w1 = (lane + 32 < NOUT) ? Ws2[k * NOUT + lane + 32] : 0.f;
        #pragma unroll
        for (int r = 0; r < 4; r++) {
            float xv = Xs2[(r0 + r) * K + k];
            acc0[r] = fmaf(xv, w0, acc0[r]);
            acc1[r] = fmaf(xv, w1, acc1[r]);
        }
    }

    float b0 = B[lane];
    float b1 = (lane + 32 < NOUT) ? B[lane + 32] : 0.f;
    #pragma unroll
    for (int r = 0; r < 4; r++) {
        int gr = row0 + r0 + r;
        if (gr >= n) continue;
        out[(size_t)gr * NOUT + lane] = acc0[r] + b0;
        if (lane + 32 < NOUT) out[(size_t)gr * NOUT + lane + 32] = acc1[r] + b1;
    }
}

// ---------------------------------------------------------------------------
extern "C" void kernel_launch(void* const* d_in, const int* in_sizes, int n_in,
                              void* d_out, int out_size) {
    const float* x    = (const float*)d_in[0];
    const int*   ei   = (const int*)d_in[1];
    const float* W0   = (const float*)d_in[2];
    const float* b0   = (const float*)d_in[3];
    const float* W1   = (const float*)d_in[4];
    const float* b1   = (const float*)d_in[5];
    const float* W2   = (const float*)d_in[6];
    const float* b2   = (const float*)d_in[7];
    const float* Wout = (const float*)d_in[8];
    const float* bout = (const float*)d_in[9];
    float* out = (float*)d_out;

    const int N = in_sizes[0] / F_IN;
    const int E = in_sizes[1] / 2;
    const int* src = ei;
    const int* dst = ei + E;

    __half *uA, *uB, *dish;
    float *dis;
    int *deg, *rowptr, *cursor, *colidx, *bsum;
    cudaGetSymbolAddress((void**)&uA,     g_uA);
    cudaGetSymbolAddress((void**)&uB,     g_uB);
    cudaGetSymbolAddress((void**)&deg,    g_deg);
    cudaGetSymbolAddress((void**)&dis,    g_dis);
    cudaGetSymbolAddress((void**)&dish,   g_dish);
    cudaGetSymbolAddress((void**)&rowptr, g_rowptr);
    cudaGetSymbolAddress((void**)&cursor, g_cursor);
    cudaGetSymbolAddress((void**)&colidx, g_colidx);
    cudaGetSymbolAddress((void**)&bsum,   g_bsum);

    const int TPB = 256;
    int gemmBlocks64 = (N + 63) / 64;               // 1563
    int scatB = (E + TPB - 1) / TPB;                // 6250
    dim3 mega_grid(gemmBlocks64 + scatB);
    dim3 layer_grid(gemmBlocks64);
    dim3 head_grid((N + 31) / 32);
    int nscan = (N + 1023) / 1024;

    // CSR prerequisite chain
    cudaMemsetAsync(deg, 0, N * sizeof(int), 0);
    count_deg_kernel<<<(E + TPB - 1) / TPB, TPB>>>(dst, E, deg);
    scan1_kernel<<<nscan, 256>>>(deg, rowptr, dis, dish, bsum, N);
    scan3_kernel<<<(N + TPB - 1) / TPB, TPB>>>(bsum, rowptr, cursor, N, nscan);

    // Layer-0 WMMA GEMM overlapped with CSR edge scatter
    gemm0_scatter_kernel<<<mega_grid, TPB>>>(x, W0, b0, uA, N,
                                             src, dst, cursor, colidx, E, gemmBlocks64);

    // Fused layers (WMMA GEMM phases)
    fused64_kernel<true><<<layer_grid, TPB>>>(rowptr, deg, colidx, dis, dish, uA, W1, b1, uB, N);
    fused64_kernel<false><<<layer_grid, TPB>>>(rowptr, deg, colidx, dis, dish, uB, W2, b2, uA, N);
    fused_head_kernel<<<head_grid, TPB>>>(rowptr, deg, colidx, dis, uA, Wout, bout, out, N);
}